// round 4
// baseline (speedup 1.0000x reference)
#include <cuda_runtime.h>
#include <cstdint>
#include <math.h>

// SphericalFilter via mma.sync.m16n8k8 tf32.
// out[p,h] = sum_k Y[p,k] * W[h,k] + b[h];  P=131072, H=1024, K=129 (pad 136)
//
// R4: 64x64 warptile (mt=4, nt=8), 128-thread CTAs (2M x 2N warps), 2 CTA/SM.
// Wfrag layout permuted so each lane's 16 accumulator columns are 16
// consecutive h values -> epilogue uses coalesced STG.128 (64B/row segments).

#define NK 129
#define NKPAD 136
#define NKC 17            // k-chunks of 8
#define H_TOT 1024
#define TILE_P 128
#define NTHREADS 128
#define NTILES_H 8        // h-loop: 8 x 128 h

#define AFRAG_FLOATS (8 * NKC * 32 * 4)   // 17408 floats = 69632 B
#define SMEM_BYTES (AFRAG_FLOATS * 4)

__device__ float Wfrag[16 * 8 * NKC * 32 * 2];   // [slot(h>>6)][nt][kc][lane][breg]

// ---------------- helpers ----------------
__device__ __forceinline__ float tf32r(float v) {
    uint32_t t;
    asm("cvt.rn.tf32.f32 %0, %1;" : "=r"(t) : "f"(v));
    return __uint_as_float(t);
}

// float index of A-fragment element (row, k) in smem (same as R3).
__device__ __forceinline__ int a_off(int row, int k) {
    int mt = row >> 4, half = (row >> 3) & 1, r4 = row & 7;
    int kc = k >> 3, khalf = (k >> 2) & 1, c = k & 3;
    return ((mt * NKC + kc) * 32 + c * 8 + r4) * 4 + half + 2 * khalf;
}

__device__ __forceinline__ void mma8(float4 a, float2 b, float* c) {
    asm volatile(
        "mma.sync.aligned.m16n8k8.row.col.f32.tf32.tf32.f32 "
        "{%0,%1,%2,%3}, {%4,%5,%6,%7}, {%8,%9}, {%0,%1,%2,%3};"
        : "+f"(c[0]), "+f"(c[1]), "+f"(c[2]), "+f"(c[3])
        : "r"(__float_as_uint(a.x)), "r"(__float_as_uint(a.y)),
          "r"(__float_as_uint(a.z)), "r"(__float_as_uint(a.w)),
          "r"(__float_as_uint(b.x)), "r"(__float_as_uint(b.y)));
}

// ---------------- W -> B-fragment reorder (permuted h mapping) ----------------
// Within each 64-h group (slot = h>>6): h_local = q*16 + nt*2 + j,
// where q = C-frag (lane&3), j = low bit; MMA column n = q*2 + j.
__global__ void wfrag_kernel(const float* __restrict__ W) {
    int idx = blockIdx.x * blockDim.x + threadIdx.x;
    if (idx >= H_TOT * NKPAD) return;
    int h = idx / NKPAD;
    int k = idx - h * NKPAD;
    float v = (k < NK) ? W[h * NK + k] : 0.0f;
    int hl = h & 63;
    int q = hl >> 4;            // lane&3 of the owning C fragment
    int rem = hl & 15;
    int nt = rem >> 1;          // ntile within 64-h warp tile
    int j = rem & 1;
    int n = q * 2 + j;          // MMA column within m16n8 tile
    int lane = n * 4 + (k & 3); // B-fragment lane ownership
    int breg = (k >> 2) & 1;
    int kc = k >> 3;
    int slot = (h >> 6) * 8 + nt;
    Wfrag[((slot * NKC + kc) * 32 + lane) * 2 + breg] = tf32r(v);
}

// ---------------- main fused kernel ----------------
__global__ __launch_bounds__(NTHREADS, 2)
void sph_mma_kernel(const float* __restrict__ x,
                    const float* __restrict__ bvec,
                    float* __restrict__ out) {
    extern __shared__ float Afrag[];
    const int tid = threadIdx.x;
    const int lane = tid & 31;
    const int wid = tid >> 5;
    const int wN = wid & 1;          // N half: 64 h
    const int wmt = (wid >> 1) * 4;  // M base in mtiles (4 mtiles = 64 rows)
    const int pbase = blockIdx.x * TILE_P;

    // ---- generate Y for 128 pixels, scattered into A-fragment layout ----
    {
        float2 tp = ((const float2*)x)[pbase + tid];
        const float theta = tp.x, phi = tp.y;
        const float ct = cosf(phi);
        const float st = sqrtf(fmaxf(1.0f - ct * ct, 0.0f));
        float pmm = 0.28209479177387814f;                 // sqrt(1/4pi)
        Afrag[a_off(tid, 64)] = tf32r(1.7320508075688772f * ct * pmm);
        const float cth = cosf(theta), sth = sinf(theta);
        float cm = 1.0f, sm = 0.0f;
        #pragma unroll 1
        for (int m = 1; m <= 64; ++m) {
            pmm *= -sqrtf((2.0f * m + 1.0f) / (2.0f * m)) * st;
            float c2 = cm * cth - sm * sth;
            float s2 = sm * cth + cm * sth;
            cm = c2; sm = s2;
            float v = sqrtf(2.0f * m + 3.0f) * ct * pmm;
            v = (m & 1) ? (-1.41421356237309515f * v) : (1.41421356237309515f * v);
            Afrag[a_off(tid, 64 + m)] = tf32r(v * cm);
            Afrag[a_off(tid, 64 - m)] = tf32r(v * sm);
        }
        #pragma unroll
        for (int k = NK; k < NKPAD; ++k) Afrag[a_off(tid, k)] = 0.0f;
    }
    __syncthreads();

    const float4* A4 = (const float4*)Afrag;
    const int aln = (lane & 3) * 8 + (lane >> 2);

    #pragma unroll 1
    for (int ht = 0; ht < NTILES_H; ++ht) {
        const int slotbase = (ht * 2 + wN) * 8;

        float acc[4][8][4];
        #pragma unroll
        for (int mt = 0; mt < 4; ++mt)
            #pragma unroll
            for (int nt = 0; nt < 8; ++nt)
                #pragma unroll
                for (int i = 0; i < 4; ++i) acc[mt][nt][i] = 0.0f;

        float2 bcur[8], bnext[8];
        #pragma unroll
        for (int nt = 0; nt < 8; ++nt)
            bcur[nt] = *(const float2*)
                &Wfrag[(((slotbase + nt) * NKC) * 32 + lane) * 2];

        #pragma unroll 1
        for (int kc = 0; kc < NKC; ++kc) {
            if (kc + 1 < NKC) {
                #pragma unroll
                for (int nt = 0; nt < 8; ++nt)
                    bnext[nt] = *(const float2*)
                        &Wfrag[(((slotbase + nt) * NKC + kc + 1) * 32 + lane) * 2];
            }
            float4 a[4];
            #pragma unroll
            for (int mt = 0; mt < 4; ++mt)
                a[mt] = A4[((wmt + mt) * NKC + kc) * 32 + aln];
            #pragma unroll
            for (int mt = 0; mt < 4; ++mt)
                #pragma unroll
                for (int nt = 0; nt < 8; ++nt)
                    mma8(a[mt], bcur[nt], acc[mt][nt]);
            #pragma unroll
            for (int nt = 0; nt < 8; ++nt) bcur[nt] = bnext[nt];
        }

        // ---- epilogue: 16 consecutive h per lane -> STG.128 x4 per row ----
        const int r = lane >> 2;
        const int hbw = ht * 128 + wN * 64 + (lane & 3) * 16;
        float4 bb[4];
        #pragma unroll
        for (int g = 0; g < 4; ++g) bb[g] = *(const float4*)&bvec[hbw + 4 * g];
        #pragma unroll
        for (int mt = 0; mt < 4; ++mt) {
            const int p0 = pbase + wmt * 16 + mt * 16 + r;
            float* o0 = &out[(size_t)p0 * H_TOT + hbw];
            float* o1 = &out[(size_t)(p0 + 8) * H_TOT + hbw];
            #pragma unroll
            for (int g = 0; g < 4; ++g) {
                // element i = g*4+e: nt = i>>1, j = i&1
                float4 v0, v1;
                v0.x = acc[mt][(g * 4 + 0) >> 1][(g * 4 + 0) & 1] + bb[g].x;
                v0.y = acc[mt][(g * 4 + 1) >> 1][(g * 4 + 1) & 1] + bb[g].y;
                v0.z = acc[mt][(g * 4 + 2) >> 1][(g * 4 + 2) & 1] + bb[g].z;
                v0.w = acc[mt][(g * 4 + 3) >> 1][(g * 4 + 3) & 1] + bb[g].w;
                v1.x = acc[mt][(g * 4 + 0) >> 1][2 + ((g * 4 + 0) & 1)] + bb[g].x;
                v1.y = acc[mt][(g * 4 + 1) >> 1][2 + ((g * 4 + 1) & 1)] + bb[g].y;
                v1.z = acc[mt][(g * 4 + 2) >> 1][2 + ((g * 4 + 2) & 1)] + bb[g].z;
                v1.w = acc[mt][(g * 4 + 3) >> 1][2 + ((g * 4 + 3) & 1)] + bb[g].w;
                *(float4*)(o0 + 4 * g) = v0;
                *(float4*)(o1 + 4 * g) = v1;
            }
        }
    }
}

extern "C" void kernel_launch(void* const* d_in, const int* in_sizes, int n_in,
                              void* d_out, int out_size) {
    const float* x = (const float*)d_in[0];   // (P, 2)
    const float* W = (const float*)d_in[1];   // (1024, 129)
    const float* b = (const float*)d_in[2];   // (1024,)
    float* out = (float*)d_out;               // (P, 1024)

    const int P = in_sizes[0] / 2;            // 131072

    wfrag_kernel<<<(H_TOT * NKPAD + 255) / 256, 256>>>(W);

    cudaFuncSetAttribute(sph_mma_kernel,
                         cudaFuncAttributeMaxDynamicSharedMemorySize, SMEM_BYTES);
    sph_mma_kernel<<<P / TILE_P, NTHREADS, SMEM_BYTES>>>(x, b, out);
}

// round 5
// speedup vs baseline: 1.2365x; 1.2365x over previous
#include <cuda_runtime.h>
#include <cstdint>
#include <math.h>

// SphericalFilter via mma.sync.m16n8k8 tf32.
// out[p,h] = sum_k Y[p,k] * W[h,k] + b[h];  P=131072, H=1024, K=129 (pad 136)
//
// R5: B-fragment loads moved to a per-warp 4-stage cp.async pipeline (smem
// ring, 2KB/stage). Warps never wait on L2 latency; no CTA barriers in the
// main loop. Warptile 64x64 (mt=4, nt=8), 128-thread CTA, 2 CTA/SM.

#define NK 129
#define NKPAD 136
#define NKC 17              // k-chunks of 8
#define H_TOT 1024
#define TILE_P 128
#define NTHREADS 128
#define NTILES_H 8
#define NBLOCKS (NTILES_H * NKC)   // 136 B-blocks per warp stream
#define STAGES 4

#define AFRAG_FLOATS (8 * NKC * 32 * 4)   // 17408 floats = 69632 B
#define BRING_FLOATS (4 * STAGES * 512)   // 4 warps x 4 stages x 2KB = 32KB
#define SMEM_BYTES ((AFRAG_FLOATS + BRING_FLOATS) * 4)

// Wfrag2: [ht][kc][wN] contiguous 2KB blocks; inside: [nt][lane][breg]
__device__ float Wfrag2[NBLOCKS * 2 * 512];

// ---------------- helpers ----------------
__device__ __forceinline__ float tf32r(float v) {
    uint32_t t;
    asm("cvt.rn.tf32.f32 %0, %1;" : "=r"(t) : "f"(v));
    return __uint_as_float(t);
}
__device__ __forceinline__ uint32_t smem_u32(const void* p) {
    uint32_t a;
    asm("{ .reg .u64 t; cvta.to.shared.u64 t, %1; cvt.u32.u64 %0, t; }" : "=r"(a) : "l"(p));
    return a;
}
__device__ __forceinline__ void cp_async16(uint32_t dst, const void* src) {
    asm volatile("cp.async.cg.shared.global [%0], [%1], 16;" :: "r"(dst), "l"(src));
}
__device__ __forceinline__ void cp_commit() {
    asm volatile("cp.async.commit_group;" ::: "memory");
}
__device__ __forceinline__ void cp_wait2() {
    asm volatile("cp.async.wait_group 2;" ::: "memory");
}

// A-fragment smem index (same layout as R3/R4).
__device__ __forceinline__ int a_off(int row, int k) {
    int mt = row >> 4, half = (row >> 3) & 1, r4 = row & 7;
    int kc = k >> 3, khalf = (k >> 2) & 1, c = k & 3;
    return ((mt * NKC + kc) * 32 + c * 8 + r4) * 4 + half + 2 * khalf;
}

__device__ __forceinline__ void mma8(float4 a, float2 b, float* c) {
    asm volatile(
        "mma.sync.aligned.m16n8k8.row.col.f32.tf32.tf32.f32 "
        "{%0,%1,%2,%3}, {%4,%5,%6,%7}, {%8,%9}, {%0,%1,%2,%3};"
        : "+f"(c[0]), "+f"(c[1]), "+f"(c[2]), "+f"(c[3])
        : "r"(__float_as_uint(a.x)), "r"(__float_as_uint(a.y)),
          "r"(__float_as_uint(a.z)), "r"(__float_as_uint(a.w)),
          "r"(__float_as_uint(b.x)), "r"(__float_as_uint(b.y)));
}

// ---------------- W -> B-fragment reorder ----------------
// h mapping inside a 64-h group: h_local = q*16 + nt*2 + j (q = C-frag lane&3).
__global__ void wfrag_kernel(const float* __restrict__ W) {
    int idx = blockIdx.x * blockDim.x + threadIdx.x;
    if (idx >= H_TOT * NKPAD) return;
    int h = idx / NKPAD;
    int k = idx - h * NKPAD;
    float v = (k < NK) ? W[h * NK + k] : 0.0f;
    int ht = h >> 7;
    int wN = (h >> 6) & 1;
    int hl = h & 63;
    int q = hl >> 4;
    int rem = hl & 15;
    int nt = rem >> 1;
    int j = rem & 1;
    int n = q * 2 + j;
    int lane = n * 4 + (k & 3);
    int breg = (k >> 2) & 1;
    int kc = k >> 3;
    Wfrag2[(((ht * NKC + kc) * 2 + wN) * 512) + (nt * 32 + lane) * 2 + breg] = tf32r(v);
}

// ---------------- main fused kernel ----------------
__global__ __launch_bounds__(NTHREADS, 2)
void sph_mma_kernel(const float* __restrict__ x,
                    const float* __restrict__ bvec,
                    float* __restrict__ out) {
    extern __shared__ float smemf[];
    float* Afrag = smemf;
    float* Bring = smemf + AFRAG_FLOATS;

    const int tid = threadIdx.x;
    const int lane = tid & 31;
    const int wid = tid >> 5;
    const int wN = wid & 1;          // N half (64 h)
    const int wmt = (wid >> 1) * 4;  // M base in mtiles
    const int pbase = blockIdx.x * TILE_P;

    // ---- generate Y for 128 pixels into A-fragment layout ----
    {
        float2 tp = ((const float2*)x)[pbase + tid];
        const float theta = tp.x, phi = tp.y;
        const float ct = cosf(phi);
        const float st = sqrtf(fmaxf(1.0f - ct * ct, 0.0f));
        float pmm = 0.28209479177387814f;                 // sqrt(1/4pi)
        Afrag[a_off(tid, 64)] = tf32r(1.7320508075688772f * ct * pmm);
        const float cth = cosf(theta), sth = sinf(theta);
        float cm = 1.0f, sm = 0.0f;
        #pragma unroll 1
        for (int m = 1; m <= 64; ++m) {
            pmm *= -sqrtf((2.0f * m + 1.0f) / (2.0f * m)) * st;
            float c2 = cm * cth - sm * sth;
            float s2 = sm * cth + cm * sth;
            cm = c2; sm = s2;
            float v = sqrtf(2.0f * m + 3.0f) * ct * pmm;
            v = (m & 1) ? (-1.41421356237309515f * v) : (1.41421356237309515f * v);
            Afrag[a_off(tid, 64 + m)] = tf32r(v * cm);
            Afrag[a_off(tid, 64 - m)] = tf32r(v * sm);
        }
        #pragma unroll
        for (int k = NK; k < NKPAD; ++k) Afrag[a_off(tid, k)] = 0.0f;
    }

    // ---- per-warp cp.async B pipeline ----
    // Stage buffer for this warp+stage: 512 floats (2KB). Each lane copies
    // 64B (4 x 16B) of the stage: bytes lane*64 .. lane*64+63.
    const uint32_t bwarp = smem_u32(Bring) + wid * (STAGES * 2048);
    const char* gsrc0 = (const char*)Wfrag2 + wN * 2048 + (size_t)lane * 64;

    // block index g (0..135) -> gmem offset g*4096 (two wN blocks per g)
    int prod = 0;
    #pragma unroll
    for (int s = 0; s < STAGES - 1; ++s) {
        const char* src = gsrc0 + (size_t)prod * 4096;
        uint32_t dst = bwarp + s * 2048 + lane * 64;
        cp_async16(dst + 0,  src + 0);
        cp_async16(dst + 16, src + 16);
        cp_async16(dst + 32, src + 32);
        cp_async16(dst + 48, src + 48);
        cp_commit();
        ++prod;
    }

    __syncthreads();   // Afrag ready (placed after pipeline start for overlap)

    const float4* A4 = (const float4*)Afrag;
    const int aln = (lane & 3) * 8 + (lane >> 2);
    int cons = 0;

    #pragma unroll 1
    for (int ht = 0; ht < NTILES_H; ++ht) {
        float acc[4][8][4];
        #pragma unroll
        for (int mt = 0; mt < 4; ++mt)
            #pragma unroll
            for (int nt = 0; nt < 8; ++nt)
                #pragma unroll
                for (int i = 0; i < 4; ++i) acc[mt][nt][i] = 0.0f;

        #pragma unroll 1
        for (int kc = 0; kc < NKC; ++kc) {
            cp_wait2();
            __syncwarp();

            const float* bs = Bring + wid * (STAGES * 512) + (cons & (STAGES - 1)) * 512;
            float2 bcur[8];
            #pragma unroll
            for (int nt = 0; nt < 8; ++nt)
                bcur[nt] = *(const float2*)&bs[(nt * 32 + lane) * 2];

            float4 a[4];
            #pragma unroll
            for (int mt = 0; mt < 4; ++mt)
                a[mt] = A4[((wmt + mt) * NKC + kc) * 32 + aln];

            // issue next block into the stage freed last iteration
            if (prod < NBLOCKS) {
                const char* src = gsrc0 + (size_t)prod * 4096;
                uint32_t dst = bwarp + (prod & (STAGES - 1)) * 2048 + lane * 64;
                cp_async16(dst + 0,  src + 0);
                cp_async16(dst + 16, src + 16);
                cp_async16(dst + 32, src + 32);
                cp_async16(dst + 48, src + 48);
                cp_commit();
                ++prod;
            }

            #pragma unroll
            for (int mt = 0; mt < 4; ++mt)
                #pragma unroll
                for (int nt = 0; nt < 8; ++nt)
                    mma8(a[mt], bcur[nt], acc[mt][nt]);
            ++cons;
        }

        // ---- epilogue: 16 consecutive h per lane -> 4x STG.128 per row ----
        const int r = lane >> 2;
        const int hbw = ht * 128 + wN * 64 + (lane & 3) * 16;
        float4 bb[4];
        #pragma unroll
        for (int g = 0; g < 4; ++g) bb[g] = *(const float4*)&bvec[hbw + 4 * g];
        #pragma unroll
        for (int mt = 0; mt < 4; ++mt) {
            const int p0 = pbase + wmt * 16 + mt * 16 + r;
            float* o0 = &out[(size_t)p0 * H_TOT + hbw];
            float* o1 = &out[(size_t)(p0 + 8) * H_TOT + hbw];
            #pragma unroll
            for (int g = 0; g < 4; ++g) {
                float4 v0, v1;
                v0.x = acc[mt][(g * 4 + 0) >> 1][(g * 4 + 0) & 1] + bb[g].x;
                v0.y = acc[mt][(g * 4 + 1) >> 1][(g * 4 + 1) & 1] + bb[g].y;
                v0.z = acc[mt][(g * 4 + 2) >> 1][(g * 4 + 2) & 1] + bb[g].z;
                v0.w = acc[mt][(g * 4 + 3) >> 1][(g * 4 + 3) & 1] + bb[g].w;
                v1.x = acc[mt][(g * 4 + 0) >> 1][2 + ((g * 4 + 0) & 1)] + bb[g].x;
                v1.y = acc[mt][(g * 4 + 1) >> 1][2 + ((g * 4 + 1) & 1)] + bb[g].y;
                v1.z = acc[mt][(g * 4 + 2) >> 1][2 + ((g * 4 + 2) & 1)] + bb[g].z;
                v1.w = acc[mt][(g * 4 + 3) >> 1][2 + ((g * 4 + 3) & 1)] + bb[g].w;
                *(float4*)(o0 + 4 * g) = v0;
                *(float4*)(o1 + 4 * g) = v1;
            }
        }
    }
}

extern "C" void kernel_launch(void* const* d_in, const int* in_sizes, int n_in,
                              void* d_out, int out_size) {
    const float* x = (const float*)d_in[0];   // (P, 2)
    const float* W = (const float*)d_in[1];   // (1024, 129)
    const float* b = (const float*)d_in[2];   // (1024,)
    float* out = (float*)d_out;               // (P, 1024)

    const int P = in_sizes[0] / 2;            // 131072

    wfrag_kernel<<<(H_TOT * NKPAD + 255) / 256, 256>>>(W);

    cudaFuncSetAttribute(sph_mma_kernel,
                         cudaFuncAttributeMaxDynamicSharedMemorySize, SMEM_BYTES);
    sph_mma_kernel<<<P / TILE_P, NTHREADS, SMEM_BYTES>>>(x, b, out);
}

// round 6
// speedup vs baseline: 2.3333x; 1.8870x over previous
#include <cuda_runtime.h>
#include <cuda_fp16.h>
#include <cstdint>
#include <math.h>

// SphericalFilter via mma.sync.m16n8k16 fp16 (fp32 accumulate).
// out[p,h] = sum_k Y[p,k] * W[h,k] + b[h];  P=131072, H=1024, K=129 (pad 144)
//
// R6: fp16 operands (same 10-bit mantissa as tf32 -> same input quantization),
// m16n8k16 halves HMMA count and LDS bytes vs R5. 256-thread CTAs, 64x32
// warptile (2M x 4N warps), 2 CTA/SM -> 16 warps/SM. Per-warp 4-stage
// cp.async ring for B fragments (1KB/stage).

#define NK 129
#define NKPAD 144
#define NKC 9               // k-chunks of 16
#define H_TOT 1024
#define TILE_P 128
#define NTHREADS 256
#define NTILES_H 8
#define NBLOCKS (NTILES_H * NKC)   // 72 B-blocks per warp stream
#define STAGES 4

#define AFRAG_HALFS (8 * NKC * 32 * 8)          // 18432 halfs = 36864 B
#define BRING_BYTES (8 * STAGES * 1024)         // 8 warps x 4 stages x 1KB
#define SMEM_BYTES (AFRAG_HALFS * 2 + BRING_BYTES)   // 69632 B

// Wfrag2: [ht][kc][wQ] contiguous 1KB blocks; inside: [nt][lane][reg] f16x2
__device__ __half Wfrag2[NBLOCKS * 4 * 512];

// ---------------- helpers ----------------
__device__ __forceinline__ uint32_t smem_u32(const void* p) {
    uint32_t a;
    asm("{ .reg .u64 t; cvta.to.shared.u64 t, %1; cvt.u32.u64 %0, t; }" : "=r"(a) : "l"(p));
    return a;
}
__device__ __forceinline__ void cp_async16(uint32_t dst, const void* src) {
    asm volatile("cp.async.cg.shared.global [%0], [%1], 16;" :: "r"(dst), "l"(src));
}
__device__ __forceinline__ void cp_commit() {
    asm volatile("cp.async.commit_group;" ::: "memory");
}
__device__ __forceinline__ void cp_wait2() {
    asm volatile("cp.async.wait_group 2;" ::: "memory");
}

// A-fragment half index for element (row, k); one LDS.128 per (mt,kc,lane).
__device__ __forceinline__ int a_off(int row, int k) {
    int mt = row >> 4, half8 = (row >> 3) & 1, g = row & 7;
    int kc = k >> 4, khalf = (k >> 3) & 1, t = (k >> 1) & 3, kbit = k & 1;
    int lane = g * 4 + t;
    int reg = khalf * 2 + half8;
    return (((mt * NKC + kc) * 32 + lane) * 4 + reg) * 2 + kbit;
}

__device__ __forceinline__ void mma16(const uint32_t* a, const uint32_t* b, float* c) {
    asm volatile(
        "mma.sync.aligned.m16n8k16.row.col.f32.f16.f16.f32 "
        "{%0,%1,%2,%3}, {%4,%5,%6,%7}, {%8,%9}, {%0,%1,%2,%3};"
        : "+f"(c[0]), "+f"(c[1]), "+f"(c[2]), "+f"(c[3])
        : "r"(a[0]), "r"(a[1]), "r"(a[2]), "r"(a[3]), "r"(b[0]), "r"(b[1]));
}

// ---------------- W -> B-fragment reorder ----------------
// h = ht*128 + wQ*32 + hl;  hl = t*8 + nt*2 + j  (t = C-frag lane&3)
__global__ void wfrag_kernel(const float* __restrict__ W) {
    int idx = blockIdx.x * blockDim.x + threadIdx.x;
    if (idx >= H_TOT * NKPAD) return;
    int h = idx / NKPAD;
    int k = idx - h * NKPAD;
    float v = (k < NK) ? W[h * NK + k] : 0.0f;
    int ht = h >> 7;
    int wQ = (h >> 5) & 3;
    int hl = h & 31;
    int t = hl >> 3;
    int rem = hl & 7;
    int nt = rem >> 1;
    int j = rem & 1;
    int n = t * 2 + j;
    int lane = n * 4 + ((k >> 1) & 3);
    int reg = (k >> 3) & 1;
    int kbit = k & 1;
    int kc = k >> 4;
    int block = (ht * NKC + kc) * 4 + wQ;
    Wfrag2[block * 512 + ((nt * 32 + lane) * 2 + reg) * 2 + kbit] = __float2half_rn(v);
}

// ---------------- main fused kernel ----------------
__global__ __launch_bounds__(NTHREADS, 2)
void sph_mma_kernel(const float* __restrict__ x,
                    const float* __restrict__ bvec,
                    float* __restrict__ out) {
    extern __shared__ __half smemh[];
    __half* Afrag = smemh;
    char* Bring = (char*)(smemh + AFRAG_HALFS);

    const int tid = threadIdx.x;
    const int lane = tid & 31;
    const int wid = tid >> 5;
    const int wQ = wid & 3;          // N quarter (32 h)
    const int wmt = (wid >> 2) * 4;  // M base in mtiles (4 mtiles = 64 rows)
    const int pbase = blockIdx.x * TILE_P;

    // ---- start B pipeline first (overlaps with Y generation) ----
    const uint32_t bwarp = smem_u32(Bring) + wid * (STAGES * 1024);
    const char* gsrc0 = (const char*)Wfrag2 + wQ * 1024 + (size_t)lane * 32;
    int prod = 0;
    #pragma unroll
    for (int s = 0; s < STAGES - 1; ++s) {
        const char* src = gsrc0 + (size_t)prod * 4096;
        uint32_t dst = bwarp + s * 1024 + lane * 32;
        cp_async16(dst + 0,  src + 0);
        cp_async16(dst + 16, src + 16);
        cp_commit();
        ++prod;
    }

    // ---- generate Y for 128 pixels into A-fragment layout (threads 0..127) ----
    if (tid < TILE_P) {
        float2 tp = ((const float2*)x)[pbase + tid];
        const float theta = tp.x, phi = tp.y;
        const float ct = cosf(phi);
        const float st = sqrtf(fmaxf(1.0f - ct * ct, 0.0f));
        float pmm = 0.28209479177387814f;                 // sqrt(1/4pi)
        Afrag[a_off(tid, 64)] = __float2half_rn(1.7320508075688772f * ct * pmm);
        const float cth = cosf(theta), sth = sinf(theta);
        float cm = 1.0f, sm = 0.0f;
        #pragma unroll 1
        for (int m = 1; m <= 64; ++m) {
            pmm *= -sqrtf((2.0f * m + 1.0f) / (2.0f * m)) * st;
            float c2 = cm * cth - sm * sth;
            float s2 = sm * cth + cm * sth;
            cm = c2; sm = s2;
            float v = sqrtf(2.0f * m + 3.0f) * ct * pmm;
            v = (m & 1) ? (-1.41421356237309515f * v) : (1.41421356237309515f * v);
            Afrag[a_off(tid, 64 + m)] = __float2half_rn(v * cm);
            Afrag[a_off(tid, 64 - m)] = __float2half_rn(v * sm);
        }
        #pragma unroll
        for (int k = NK; k < NKPAD; ++k) Afrag[a_off(tid, k)] = __half(0.0f);
    }
    __syncthreads();

    const uint32_t abase = smem_u32(Afrag);
    int cons = 0;

    #pragma unroll 1
    for (int ht = 0; ht < NTILES_H; ++ht) {
        float acc[4][4][4];
        #pragma unroll
        for (int mt = 0; mt < 4; ++mt)
            #pragma unroll
            for (int nt = 0; nt < 4; ++nt)
                #pragma unroll
                for (int i = 0; i < 4; ++i) acc[mt][nt][i] = 0.0f;

        #pragma unroll 1
        for (int kc = 0; kc < NKC; ++kc) {
            cp_wait2();
            __syncwarp();

            const uint32_t* bs = (const uint32_t*)
                (Bring + wid * (STAGES * 1024) + (cons & (STAGES - 1)) * 1024);
            uint32_t bfr[4][2];
            #pragma unroll
            for (int nt = 0; nt < 4; ++nt) {
                bfr[nt][0] = bs[(nt * 32 + lane) * 2 + 0];
                bfr[nt][1] = bs[(nt * 32 + lane) * 2 + 1];
            }

            uint32_t afr[4][4];
            #pragma unroll
            for (int mt = 0; mt < 4; ++mt) {
                uint32_t addr = abase + ((((wmt + mt) * NKC + kc) * 32 + lane) * 4) * 4;
                asm volatile("ld.shared.v4.u32 {%0,%1,%2,%3}, [%4];"
                             : "=r"(afr[mt][0]), "=r"(afr[mt][1]),
                               "=r"(afr[mt][2]), "=r"(afr[mt][3])
                             : "r"(addr));
            }

            if (prod < NBLOCKS) {
                const char* src = gsrc0 + (size_t)prod * 4096;
                uint32_t dst = bwarp + (prod & (STAGES - 1)) * 1024 + lane * 32;
                cp_async16(dst + 0,  src + 0);
                cp_async16(dst + 16, src + 16);
                cp_commit();
                ++prod;
            }

            #pragma unroll
            for (int mt = 0; mt < 4; ++mt)
                #pragma unroll
                for (int nt = 0; nt < 4; ++nt)
                    mma16(afr[mt], bfr[nt], acc[mt][nt]);
            ++cons;
        }

        // ---- epilogue: 8 consecutive h per lane -> 2x STG.128 per row ----
        const int g = lane >> 2;
        const int hb = ht * 128 + wQ * 32 + (lane & 3) * 8;
        float4 bb0 = *(const float4*)&bvec[hb];
        float4 bb1 = *(const float4*)&bvec[hb + 4];
        #pragma unroll
        for (int mt = 0; mt < 4; ++mt) {
            const int p0 = pbase + (wmt + mt) * 16 + g;
            float* o0 = &out[(size_t)p0 * H_TOT + hb];
            float* o1 = &out[(size_t)(p0 + 8) * H_TOT + hb];
            float4 v0, v1;
            // row g
            v0.x = acc[mt][0][0] + bb0.x;  v0.y = acc[mt][0][1] + bb0.y;
            v0.z = acc[mt][1][0] + bb0.z;  v0.w = acc[mt][1][1] + bb0.w;
            v1.x = acc[mt][2][0] + bb1.x;  v1.y = acc[mt][2][1] + bb1.y;
            v1.z = acc[mt][3][0] + bb1.z;  v1.w = acc[mt][3][1] + bb1.w;
            *(float4*)(o0 + 0) = v0;
            *(float4*)(o0 + 4) = v1;
            // row g+8
            v0.x = acc[mt][0][2] + bb0.x;  v0.y = acc[mt][0][3] + bb0.y;
            v0.z = acc[mt][1][2] + bb0.z;  v0.w = acc[mt][1][3] + bb0.w;
            v1.x = acc[mt][2][2] + bb1.x;  v1.y = acc[mt][2][3] + bb1.y;
            v1.z = acc[mt][3][2] + bb1.z;  v1.w = acc[mt][3][3] + bb1.w;
            *(float4*)(o1 + 0) = v0;
            *(float4*)(o1 + 4) = v1;
        }
    }
}

extern "C" void kernel_launch(void* const* d_in, const int* in_sizes, int n_in,
                              void* d_out, int out_size) {
    const float* x = (const float*)d_in[0];   // (P, 2)
    const float* W = (const float*)d_in[1];   // (1024, 129)
    const float* b = (const float*)d_in[2];   // (1024,)
    float* out = (float*)d_out;               // (P, 1024)

    const int P = in_sizes[0] / 2;            // 131072

    wfrag_kernel<<<(H_TOT * NKPAD + 255) / 256, 256>>>(W);

    cudaFuncSetAttribute(sph_mma_kernel,
                         cudaFuncAttributeMaxDynamicSharedMemorySize, SMEM_BYTES);
    sph_mma_kernel<<<P / TILE_P, NTHREADS, SMEM_BYTES>>>(x, b, out);
}

// round 7
// speedup vs baseline: 2.4004x; 1.0288x over previous
#include <cuda_runtime.h>
#include <cuda_fp16.h>
#include <cstdint>
#include <math.h>

// SphericalFilter via mma.sync.m16n8k16 fp16 (fp32 accumulate).
// out[p,h] = sum_k Y[p,k] * W[h,k] + b[h];  P=131072, H=1024, K=129 (pad 144)
//
// R7: single-warp software pipeline. Register double-buffered B fragments
// (prefetch kc+1 after wait_group 1), fully unrolled kc loop, LDS.64 B loads,
// streaming epilogue stores. 256-thread CTAs, 64x32 warptile, 2 CTA/SM.

#define NK 129
#define NKPAD 144
#define NKC 9               // k-chunks of 16
#define H_TOT 1024
#define TILE_P 128
#define NTHREADS 256
#define NTILES_H 8
#define NBLOCKS (NTILES_H * NKC)   // 72 B-blocks per warp stream
#define STAGES 4

#define AFRAG_HALFS (8 * NKC * 32 * 8)          // 18432 halfs = 36864 B
#define BRING_BYTES (8 * STAGES * 1024)         // 8 warps x 4 stages x 1KB
#define SMEM_BYTES (AFRAG_HALFS * 2 + BRING_BYTES)   // 69632 B

// Wfrag2: [ht][kc][wQ] contiguous 1KB blocks; inside: [nt][lane][reg] f16x2
__device__ __half Wfrag2[NBLOCKS * 4 * 512];

// ---------------- helpers ----------------
__device__ __forceinline__ uint32_t smem_u32(const void* p) {
    uint32_t a;
    asm("{ .reg .u64 t; cvta.to.shared.u64 t, %1; cvt.u32.u64 %0, t; }" : "=r"(a) : "l"(p));
    return a;
}
__device__ __forceinline__ void cp_async16(uint32_t dst, const void* src) {
    asm volatile("cp.async.cg.shared.global [%0], [%1], 16;" :: "r"(dst), "l"(src));
}
__device__ __forceinline__ void cp_commit() {
    asm volatile("cp.async.commit_group;" ::: "memory");
}
__device__ __forceinline__ void cp_wait1() {
    asm volatile("cp.async.wait_group 1;" ::: "memory");
}
__device__ __forceinline__ void cp_wait2() {
    asm volatile("cp.async.wait_group 2;" ::: "memory");
}

// A-fragment half index for element (row, k); one LDS.128 per (mt,kc,lane).
__device__ __forceinline__ int a_off(int row, int k) {
    int mt = row >> 4, half8 = (row >> 3) & 1, g = row & 7;
    int kc = k >> 4, khalf = (k >> 3) & 1, t = (k >> 1) & 3, kbit = k & 1;
    int lane = g * 4 + t;
    int reg = khalf * 2 + half8;
    return (((mt * NKC + kc) * 32 + lane) * 4 + reg) * 2 + kbit;
}

__device__ __forceinline__ void mma16(const uint32_t* a, const uint32_t* b, float* c) {
    asm volatile(
        "mma.sync.aligned.m16n8k16.row.col.f32.f16.f16.f32 "
        "{%0,%1,%2,%3}, {%4,%5,%6,%7}, {%8,%9}, {%0,%1,%2,%3};"
        : "+f"(c[0]), "+f"(c[1]), "+f"(c[2]), "+f"(c[3])
        : "r"(a[0]), "r"(a[1]), "r"(a[2]), "r"(a[3]), "r"(b[0]), "r"(b[1]));
}

__device__ __forceinline__ void stcs4(float* p, float4 v) {
    asm volatile("st.global.cs.v4.f32 [%0], {%1,%2,%3,%4};"
                 :: "l"(p), "f"(v.x), "f"(v.y), "f"(v.z), "f"(v.w) : "memory");
}

// ---------------- W -> B-fragment reorder ----------------
// h = ht*128 + wQ*32 + hl;  hl = t*8 + nt*2 + j  (t = C-frag lane&3)
__global__ void wfrag_kernel(const float* __restrict__ W) {
    int idx = blockIdx.x * blockDim.x + threadIdx.x;
    if (idx >= H_TOT * NKPAD) return;
    int h = idx / NKPAD;
    int k = idx - h * NKPAD;
    float v = (k < NK) ? W[h * NK + k] : 0.0f;
    int ht = h >> 7;
    int wQ = (h >> 5) & 3;
    int hl = h & 31;
    int t = hl >> 3;
    int rem = hl & 7;
    int nt = rem >> 1;
    int j = rem & 1;
    int n = t * 2 + j;
    int lane = n * 4 + ((k >> 1) & 3);
    int reg = (k >> 3) & 1;
    int kbit = k & 1;
    int kc = k >> 4;
    int block = (ht * NKC + kc) * 4 + wQ;
    Wfrag2[block * 512 + ((nt * 32 + lane) * 2 + reg) * 2 + kbit] = __float2half_rn(v);
}

// ---------------- main fused kernel ----------------
__global__ __launch_bounds__(NTHREADS, 2)
void sph_mma_kernel(const float* __restrict__ x,
                    const float* __restrict__ bvec,
                    float* __restrict__ out) {
    extern __shared__ __half smemh[];
    __half* Afrag = smemh;
    char* Bring = (char*)(smemh + AFRAG_HALFS);

    const int tid = threadIdx.x;
    const int lane = tid & 31;
    const int wid = tid >> 5;
    const int wQ = wid & 3;          // N quarter (32 h)
    const int wmt = (wid >> 2) * 4;  // M base in mtiles (4 mtiles = 64 rows)
    const int pbase = blockIdx.x * TILE_P;

    // ---- start B pipeline first (overlaps with Y generation) ----
    const uint32_t bwarp = smem_u32(Bring) + wid * (STAGES * 1024);
    const char* gsrc0 = (const char*)Wfrag2 + wQ * 1024 + (size_t)lane * 32;
    int prod = 0;
    #pragma unroll
    for (int s = 0; s < STAGES - 1; ++s) {
        const char* src = gsrc0 + (size_t)prod * 4096;
        uint32_t dst = bwarp + s * 1024 + lane * 32;
        cp_async16(dst + 0,  src + 0);
        cp_async16(dst + 16, src + 16);
        cp_commit();
        ++prod;
    }

    // ---- generate Y for 128 pixels into A-fragment layout (threads 0..127) ----
    if (tid < TILE_P) {
        float2 tp = ((const float2*)x)[pbase + tid];
        const float theta = tp.x, phi = tp.y;
        const float ct = cosf(phi);
        const float st = sqrtf(fmaxf(1.0f - ct * ct, 0.0f));
        float pmm = 0.28209479177387814f;                 // sqrt(1/4pi)
        Afrag[a_off(tid, 64)] = __float2half_rn(1.7320508075688772f * ct * pmm);
        const float cth = cosf(theta), sth = sinf(theta);
        float cm = 1.0f, sm = 0.0f;
        #pragma unroll 1
        for (int m = 1; m <= 64; ++m) {
            pmm *= -sqrtf((2.0f * m + 1.0f) / (2.0f * m)) * st;
            float c2 = cm * cth - sm * sth;
            float s2 = sm * cth + cm * sth;
            cm = c2; sm = s2;
            float v = sqrtf(2.0f * m + 3.0f) * ct * pmm;
            v = (m & 1) ? (-1.41421356237309515f * v) : (1.41421356237309515f * v);
            Afrag[a_off(tid, 64 + m)] = __float2half_rn(v * cm);
            Afrag[a_off(tid, 64 - m)] = __float2half_rn(v * sm);
        }
        #pragma unroll
        for (int k = NK; k < NKPAD; ++k) Afrag[a_off(tid, k)] = __half(0.0f);
    }
    __syncthreads();

    const uint32_t abase = smem_u32(Afrag);
    const uint32_t bbase = smem_u32(Bring) + wid * (STAGES * 1024) + lane * 8;

    // ---- prologue: load B block 0 into registers ----
    uint32_t bfr[4][2], bnx[4][2];
    cp_wait2();
    __syncwarp();
    #pragma unroll
    for (int nt = 0; nt < 4; ++nt)
        asm volatile("ld.shared.v2.u32 {%0,%1}, [%2];"
                     : "=r"(bfr[nt][0]), "=r"(bfr[nt][1])
                     : "r"(bbase + nt * 256));

    #pragma unroll 1
    for (int ht = 0; ht < NTILES_H; ++ht) {
        float acc[4][4][4];
        #pragma unroll
        for (int mt = 0; mt < 4; ++mt)
            #pragma unroll
            for (int nt = 0; nt < 4; ++nt)
                #pragma unroll
                for (int i = 0; i < 4; ++i) acc[mt][nt][i] = 0.0f;

        #pragma unroll
        for (int kc = 0; kc < NKC; ++kc) {
            const int g = ht * NKC + kc;          // global block index

            // prefetch next block's B fragments into registers
            if (g + 1 < NBLOCKS) {
                cp_wait1();
                __syncwarp();
                const uint32_t bs = bbase + ((g + 1) & (STAGES - 1)) * 1024;
                #pragma unroll
                for (int nt = 0; nt < 4; ++nt)
                    asm volatile("ld.shared.v2.u32 {%0,%1}, [%2];"
                                 : "=r"(bnx[nt][0]), "=r"(bnx[nt][1])
                                 : "r"(bs + nt * 256));
            }

            // keep the cp.async stream fed
            if (prod < NBLOCKS) {
                const char* src = gsrc0 + (size_t)prod * 4096;
                uint32_t dst = bwarp + (prod & (STAGES - 1)) * 1024 + lane * 32;
                cp_async16(dst + 0,  src + 0);
                cp_async16(dst + 16, src + 16);
                cp_commit();
                ++prod;
            }

            // A fragments for this kc
            uint32_t afr[4][4];
            #pragma unroll
            for (int mt = 0; mt < 4; ++mt) {
                uint32_t addr = abase + ((((wmt + mt) * NKC + kc) * 32 + lane) * 4) * 4;
                asm volatile("ld.shared.v4.u32 {%0,%1,%2,%3}, [%4];"
                             : "=r"(afr[mt][0]), "=r"(afr[mt][1]),
                               "=r"(afr[mt][2]), "=r"(afr[mt][3])
                             : "r"(addr));
            }

            #pragma unroll
            for (int mt = 0; mt < 4; ++mt)
                #pragma unroll
                for (int nt = 0; nt < 4; ++nt)
                    mma16(afr[mt], bfr[nt], acc[mt][nt]);

            #pragma unroll
            for (int nt = 0; nt < 4; ++nt) {
                bfr[nt][0] = bnx[nt][0];
                bfr[nt][1] = bnx[nt][1];
            }
        }

        // ---- epilogue: 8 consecutive h per lane -> 2x streaming STG.128/row ----
        const int g = lane >> 2;
        const int hb = ht * 128 + wQ * 32 + (lane & 3) * 8;
        float4 bb0 = *(const float4*)&bvec[hb];
        float4 bb1 = *(const float4*)&bvec[hb + 4];
        #pragma unroll
        for (int mt = 0; mt < 4; ++mt) {
            const int p0 = pbase + (wmt + mt) * 16 + g;
            float* o0 = &out[(size_t)p0 * H_TOT + hb];
            float* o1 = &out[(size_t)(p0 + 8) * H_TOT + hb];
            float4 v0, v1;
            // row g
            v0.x = acc[mt][0][0] + bb0.x;  v0.y = acc[mt][0][1] + bb0.y;
            v0.z = acc[mt][1][0] + bb0.z;  v0.w = acc[mt][1][1] + bb0.w;
            v1.x = acc[mt][2][0] + bb1.x;  v1.y = acc[mt][2][1] + bb1.y;
            v1.z = acc[mt][3][0] + bb1.z;  v1.w = acc[mt][3][1] + bb1.w;
            stcs4(o0 + 0, v0);
            stcs4(o0 + 4, v1);
            // row g+8
            v0.x = acc[mt][0][2] + bb0.x;  v0.y = acc[mt][0][3] + bb0.y;
            v0.z = acc[mt][1][2] + bb0.z;  v0.w = acc[mt][1][3] + bb0.w;
            v1.x = acc[mt][2][2] + bb1.x;  v1.y = acc[mt][2][3] + bb1.y;
            v1.z = acc[mt][3][2] + bb1.z;  v1.w = acc[mt][3][3] + bb1.w;
            stcs4(o1 + 0, v0);
            stcs4(o1 + 4, v1);
        }
    }
}

extern "C" void kernel_launch(void* const* d_in, const int* in_sizes, int n_in,
                              void* d_out, int out_size) {
    const float* x = (const float*)d_in[0];   // (P, 2)
    const float* W = (const float*)d_in[1];   // (1024, 129)
    const float* b = (const float*)d_in[2];   // (1024,)
    float* out = (float*)d_out;               // (P, 1024)

    const int P = in_sizes[0] / 2;            // 131072

    wfrag_kernel<<<(H_TOT * NKPAD + 255) / 256, 256>>>(W);

    cudaFuncSetAttribute(sph_mma_kernel,
                         cudaFuncAttributeMaxDynamicSharedMemorySize, SMEM_BYTES);
    sph_mma_kernel<<<P / TILE_P, NTHREADS, SMEM_BYTES>>>(x, b, out);
}

// round 8
// speedup vs baseline: 2.5166x; 1.0484x over previous
#include <cuda_runtime.h>
#include <cuda_fp16.h>
#include <cstdint>
#include <math.h>

// SphericalFilter via mma.sync.m16n8k16 fp16 (fp32 accumulate).
// out[p,h] = sum_k Y[p,k] * W[h,k] + b[h];  P=131072, H=1024, K=129 (pad 144)
//
// R8: CTA-level B staging via cp.async.bulk (async engine, no per-thread STS
// wavefronts) into an 8-stage x 4KB shared ring with full/empty mbarriers.
// One copy serves all 8 warps (halves B L2 traffic vs per-warp rings).
// 256-thread CTAs, 64x32 warptile, 2 CTA/SM.

#define NK 129
#define NKPAD 144
#define NKC 9               // k-chunks of 16
#define H_TOT 1024
#define TILE_P 128
#define NTHREADS 256
#define NTILES_H 8
#define NBLOCKS (NTILES_H * NKC)   // 72 4KB B-blocks per CTA
#define STAGES 8
#define PROD_AHEAD 4

#define AFRAG_HALFS (8 * NKC * 32 * 8)          // 18432 halfs = 36864 B
#define RING_BYTES (STAGES * 4096)              // 32768 B
#define RING_OFF (AFRAG_HALFS * 2)              // 36864
#define MBAR_OFF (RING_OFF + RING_BYTES)        // 69632 (full[8] then empty[8])
#define SMEM_BYTES (MBAR_OFF + 128)             // 69760 B

// Wfrag2: [block g = ht*9+kc][wQ][nt][lane][reg] f16x2; 4KB per block
__device__ __half Wfrag2[NBLOCKS * 4 * 512];

// ---------------- helpers ----------------
__device__ __forceinline__ uint32_t smem_u32(const void* p) {
    uint32_t a;
    asm("{ .reg .u64 t; cvta.to.shared.u64 t, %1; cvt.u32.u64 %0, t; }" : "=r"(a) : "l"(p));
    return a;
}
__device__ __forceinline__ void mbar_init(uint32_t mbar, uint32_t cnt) {
    asm volatile("mbarrier.init.shared.b64 [%0], %1;" :: "r"(mbar), "r"(cnt) : "memory");
}
__device__ __forceinline__ void mbar_arrive(uint32_t mbar) {
    asm volatile("mbarrier.arrive.shared.b64 _, [%0];" :: "r"(mbar) : "memory");
}
__device__ __forceinline__ void mbar_expect_tx(uint32_t mbar, uint32_t bytes) {
    asm volatile("mbarrier.arrive.expect_tx.shared.b64 _, [%0], %1;"
                 :: "r"(mbar), "r"(bytes) : "memory");
}
__device__ __forceinline__ void mbar_wait(uint32_t mbar, uint32_t parity) {
    asm volatile(
        "{\n\t.reg .pred P;\n"
        "WL_%=:\n\t"
        "mbarrier.try_wait.parity.acquire.cta.shared::cta.b64 P, [%0], %1, 0x989680;\n\t"
        "@P bra.uni WD_%=;\n\t"
        "bra.uni WL_%=;\n"
        "WD_%=:\n\t}"
        :: "r"(mbar), "r"(parity) : "memory");
}
__device__ __forceinline__ void bulk_copy(uint32_t dst, const void* src,
                                          uint32_t bytes, uint32_t mbar) {
    asm volatile(
        "cp.async.bulk.shared::cta.global.mbarrier::complete_tx::bytes [%0], [%1], %2, [%3];"
        :: "r"(dst), "l"(src), "r"(bytes), "r"(mbar) : "memory");
}

// A-fragment half index for element (row, k); one LDS.128 per (mt,kc,lane).
__device__ __forceinline__ int a_off(int row, int k) {
    int mt = row >> 4, half8 = (row >> 3) & 1, g = row & 7;
    int kc = k >> 4, khalf = (k >> 3) & 1, t = (k >> 1) & 3, kbit = k & 1;
    int lane = g * 4 + t;
    int reg = khalf * 2 + half8;
    return (((mt * NKC + kc) * 32 + lane) * 4 + reg) * 2 + kbit;
}

__device__ __forceinline__ void mma16(const uint32_t* a, const uint32_t* b, float* c) {
    asm volatile(
        "mma.sync.aligned.m16n8k16.row.col.f32.f16.f16.f32 "
        "{%0,%1,%2,%3}, {%4,%5,%6,%7}, {%8,%9}, {%0,%1,%2,%3};"
        : "+f"(c[0]), "+f"(c[1]), "+f"(c[2]), "+f"(c[3])
        : "r"(a[0]), "r"(a[1]), "r"(a[2]), "r"(a[3]), "r"(b[0]), "r"(b[1]));
}

__device__ __forceinline__ void stcs4(float* p, float4 v) {
    asm volatile("st.global.cs.v4.f32 [%0], {%1,%2,%3,%4};"
                 :: "l"(p), "f"(v.x), "f"(v.y), "f"(v.z), "f"(v.w) : "memory");
}

// ---------------- W -> B-fragment reorder ----------------
// h = ht*128 + wQ*32 + hl;  hl = t*8 + nt*2 + j  (t = C-frag lane&3)
__global__ void wfrag_kernel(const float* __restrict__ W) {
    int idx = blockIdx.x * blockDim.x + threadIdx.x;
    if (idx >= H_TOT * NKPAD) return;
    int h = idx / NKPAD;
    int k = idx - h * NKPAD;
    float v = (k < NK) ? W[h * NK + k] : 0.0f;
    int ht = h >> 7;
    int wQ = (h >> 5) & 3;
    int hl = h & 31;
    int t = hl >> 3;
    int rem = hl & 7;
    int nt = rem >> 1;
    int j = rem & 1;
    int n = t * 2 + j;
    int lane = n * 4 + ((k >> 1) & 3);
    int reg = (k >> 3) & 1;
    int kbit = k & 1;
    int kc = k >> 4;
    int block = (ht * NKC + kc) * 4 + wQ;
    Wfrag2[block * 512 + ((nt * 32 + lane) * 2 + reg) * 2 + kbit] = __float2half_rn(v);
}

// ---------------- main fused kernel ----------------
__global__ __launch_bounds__(NTHREADS, 2)
void sph_mma_kernel(const float* __restrict__ x,
                    const float* __restrict__ bvec,
                    float* __restrict__ out) {
    extern __shared__ __half smemh[];
    __half* Afrag = smemh;
    const uint32_t sbase = smem_u32(smemh);
    const uint32_t ring = sbase + RING_OFF;
    const uint32_t full0 = sbase + MBAR_OFF;
    const uint32_t empty0 = sbase + MBAR_OFF + 64;

    const int tid = threadIdx.x;
    const int lane = tid & 31;
    const int wid = tid >> 5;
    const int wQ = wid & 3;          // N quarter (32 h)
    const int wmt = (wid >> 2) * 4;  // M base in mtiles (4 mtiles = 64 rows)
    const int pbase = blockIdx.x * TILE_P;
    const bool producer = (tid == 0);

    // ---- init mbarriers ----
    if (tid == 0) {
        #pragma unroll
        for (int s = 0; s < STAGES; ++s) {
            mbar_init(full0 + s * 8, 1);    // expect_tx based
            mbar_init(empty0 + s * 8, 8);   // 8 consumer warps
        }
    }
    __syncthreads();

    // ---- producer prologue: first PROD_AHEAD blocks ----
    if (producer) {
        #pragma unroll
        for (int g = 0; g < PROD_AHEAD; ++g) {
            mbar_expect_tx(full0 + g * 8, 4096);
            bulk_copy(ring + g * 4096, (const char*)Wfrag2 + (size_t)g * 4096,
                      4096, full0 + g * 8);
        }
    }

    // ---- generate Y for 128 pixels into A-fragment layout (threads 0..127) ----
    if (tid < TILE_P) {
        float2 tp = ((const float2*)x)[pbase + tid];
        const float theta = tp.x, phi = tp.y;
        const float ct = cosf(phi);
        const float st = sqrtf(fmaxf(1.0f - ct * ct, 0.0f));
        float pmm = 0.28209479177387814f;                 // sqrt(1/4pi)
        Afrag[a_off(tid, 64)] = __float2half_rn(1.7320508075688772f * ct * pmm);
        const float cth = cosf(theta), sth = sinf(theta);
        float cm = 1.0f, sm = 0.0f;
        #pragma unroll 1
        for (int m = 1; m <= 64; ++m) {
            pmm *= -sqrtf((2.0f * m + 1.0f) / (2.0f * m)) * st;
            float c2 = cm * cth - sm * sth;
            float s2 = sm * cth + cm * sth;
            cm = c2; sm = s2;
            float v = sqrtf(2.0f * m + 3.0f) * ct * pmm;
            v = (m & 1) ? (-1.41421356237309515f * v) : (1.41421356237309515f * v);
            Afrag[a_off(tid, 64 + m)] = __float2half_rn(v * cm);
            Afrag[a_off(tid, 64 - m)] = __float2half_rn(v * sm);
        }
        #pragma unroll
        for (int k = NK; k < NKPAD; ++k) Afrag[a_off(tid, k)] = __half(0.0f);
    }
    __syncthreads();

    const uint32_t abase = sbase;   // Afrag at smem offset 0

    #pragma unroll 1
    for (int ht = 0; ht < NTILES_H; ++ht) {
        float acc[4][4][4];
        #pragma unroll
        for (int mt = 0; mt < 4; ++mt)
            #pragma unroll
            for (int nt = 0; nt < 4; ++nt)
                #pragma unroll
                for (int i = 0; i < 4; ++i) acc[mt][nt][i] = 0.0f;

        #pragma unroll
        for (int kc = 0; kc < NKC; ++kc) {
            const int g = ht * NKC + kc;       // global block index
            const int stage = g & (STAGES - 1);

            // producer: issue block g+PROD_AHEAD into its stage
            if (producer) {
                const int gp = g + PROD_AHEAD;
                if (gp < NBLOCKS) {
                    const int sp = gp & (STAGES - 1);
                    const int u = gp >> 3;     // usage index of stage sp
                    if (u >= 1) mbar_wait(empty0 + sp * 8, (u - 1) & 1);
                    mbar_expect_tx(full0 + sp * 8, 4096);
                    bulk_copy(ring + sp * 4096,
                              (const char*)Wfrag2 + (size_t)gp * 4096,
                              4096, full0 + sp * 8);
                }
            }

            // consumer: wait for block g
            mbar_wait(full0 + stage * 8, (g >> 3) & 1);

            // B fragments for this warp's wQ slice
            const uint32_t bs = ring + stage * 4096 + wQ * 1024 + lane * 8;
            uint32_t bfr[4][2];
            #pragma unroll
            for (int nt = 0; nt < 4; ++nt)
                asm volatile("ld.shared.v2.u32 {%0,%1}, [%2];"
                             : "=r"(bfr[nt][0]), "=r"(bfr[nt][1])
                             : "r"(bs + nt * 256));

            // A fragments for this kc
            uint32_t afr[4][4];
            #pragma unroll
            for (int mt = 0; mt < 4; ++mt) {
                uint32_t addr = abase + ((((wmt + mt) * NKC + kc) * 32 + lane) * 4) * 4;
                asm volatile("ld.shared.v4.u32 {%0,%1,%2,%3}, [%4];"
                             : "=r"(afr[mt][0]), "=r"(afr[mt][1]),
                               "=r"(afr[mt][2]), "=r"(afr[mt][3])
                             : "r"(addr));
            }

            #pragma unroll
            for (int mt = 0; mt < 4; ++mt)
                #pragma unroll
                for (int nt = 0; nt < 4; ++nt)
                    mma16(afr[mt], bfr[nt], acc[mt][nt]);

            // release the stage (B values are consumed into acc by mma.sync)
            if (lane == 0) mbar_arrive(empty0 + stage * 8);
        }

        // ---- epilogue: 8 consecutive h per lane -> 2x streaming STG.128/row ----
        const int g = lane >> 2;
        const int hb = ht * 128 + wQ * 32 + (lane & 3) * 8;
        float4 bb0 = *(const float4*)&bvec[hb];
        float4 bb1 = *(const float4*)&bvec[hb + 4];
        #pragma unroll
        for (int mt = 0; mt < 4; ++mt) {
            const int p0 = pbase + (wmt + mt) * 16 + g;
            float* o0 = &out[(size_t)p0 * H_TOT + hb];
            float* o1 = &out[(size_t)(p0 + 8) * H_TOT + hb];
            float4 v0, v1;
            // row g
            v0.x = acc[mt][0][0] + bb0.x;  v0.y = acc[mt][0][1] + bb0.y;
            v0.z = acc[mt][1][0] + bb0.z;  v0.w = acc[mt][1][1] + bb0.w;
            v1.x = acc[mt][2][0] + bb1.x;  v1.y = acc[mt][2][1] + bb1.y;
            v1.z = acc[mt][3][0] + bb1.z;  v1.w = acc[mt][3][1] + bb1.w;
            stcs4(o0 + 0, v0);
            stcs4(o0 + 4, v1);
            // row g+8
            v0.x = acc[mt][0][2] + bb0.x;  v0.y = acc[mt][0][3] + bb0.y;
            v0.z = acc[mt][1][2] + bb0.z;  v0.w = acc[mt][1][3] + bb0.w;
            v1.x = acc[mt][2][2] + bb1.x;  v1.y = acc[mt][2][3] + bb1.y;
            v1.z = acc[mt][3][2] + bb1.z;  v1.w = acc[mt][3][3] + bb1.w;
            stcs4(o1 + 0, v0);
            stcs4(o1 + 4, v1);
        }
    }
}

extern "C" void kernel_launch(void* const* d_in, const int* in_sizes, int n_in,
                              void* d_out, int out_size) {
    const float* x = (const float*)d_in[0];   // (P, 2)
    const float* W = (const float*)d_in[1];   // (1024, 129)
    const float* b = (const float*)d_in[2];   // (1024,)
    float* out = (float*)d_out;               // (P, 1024)

    const int P = in_sizes[0] / 2;            // 131072

    wfrag_kernel<<<(H_TOT * NKPAD + 255) / 256, 256>>>(W);

    cudaFuncSetAttribute(sph_mma_kernel,
                         cudaFuncAttributeMaxDynamicSharedMemorySize, SMEM_BYTES);
    sph_mma_kernel<<<P / TILE_P, NTHREADS, SMEM_BYTES>>>(x, b, out);
}